// round 4
// baseline (speedup 1.0000x reference)
#include <cuda_runtime.h>
#include <math.h>

#define BB   64
#define NNODE 1024
#define FIN  195
#define HH   128
#define OO   64
#define KK1  512
#define KK2  256

// ---------------- scratch (device globals; no allocation allowed) ----------------
__device__ float          g_xc[(size_t)BB*NNODE*FIN];
__device__ float          g_d[BB*NNODE];
__device__ unsigned char  g_A[(size_t)BB*NNODE*NNODE];
__device__ unsigned short g_nbr[(size_t)BB*NNODE*NNODE];
__device__ int            g_deg[BB*NNODE];
__device__ float          g_agg1[(size_t)BB*NNODE*FIN];
__device__ float          g_h1[(size_t)BB*NNODE*HH];
__device__ float          g_srel[BB*NNODE];
__device__ float          g_sroot[BB*NNODE];
__device__ float          g_score[BB*NNODE];
__device__ int            g_idx1[BB*KK1];
__device__ float          g_x1[(size_t)BB*KK1*HH];
__device__ unsigned char  g_A1[(size_t)BB*KK1*KK1];
__device__ unsigned short g_nbr2[(size_t)BB*KK1*KK1];
__device__ int            g_deg2[BB*KK1];
__device__ float          g_agg2[(size_t)BB*KK1*HH];
__device__ float          g_h2[(size_t)BB*KK1*OO];
__device__ float          g_srel2[BB*KK1];
__device__ float          g_sroot2[BB*KK1];
__device__ float          g_score2[BB*KK1];
__device__ int            g_idx2[BB*KK2];
__device__ float          g_tanh2[BB*KK2];
__device__ float          g_pool[BB*OO];

// ---------------- 1) center rows, compute d = sqrt(max(sumsq,1e-12)) ----------------
__global__ void k_center(const float* __restrict__ x) {
    int row = blockIdx.x;           // b*N + n
    int t = threadIdx.x;            // 256
    __shared__ float red[256];
    float v = 0.f;
    if (t < FIN) v = x[(size_t)row*FIN + t];
    red[t] = v;
    __syncthreads();
    for (int s = 128; s > 0; s >>= 1) { if (t < s) red[t] += red[t+s]; __syncthreads(); }
    float mean = red[0] * (1.0f/FIN);
    __syncthreads();
    float c = v - mean;
    if (t < FIN) g_xc[(size_t)row*FIN + t] = c;
    red[t] = (t < FIN) ? c*c : 0.f;
    __syncthreads();
    for (int s = 128; s > 0; s >>= 1) { if (t < s) red[t] += red[t+s]; __syncthreads(); }
    if (t == 0) g_d[row] = sqrtf(fmaxf(red[0], 1e-12f));
}

// ---------------- 2) cov GEMM (symmetric, upper-triangle blocks) + threshold -> A ----------------
__global__ void k_cov() {
    int b = blockIdx.z;
    int bi = blockIdx.x, bj = blockIdx.y;
    if (bj < bi) return;
    __shared__ float As[16][68];
    __shared__ float Bs[16][68];
    int tid = threadIdx.x;                 // 256
    int tx = tid & 15, ty = tid >> 4;
    const float* xc = g_xc + (size_t)b*NNODE*FIN;
    float acc[4][4];
#pragma unroll
    for (int r = 0; r < 4; r++)
#pragma unroll
        for (int c = 0; c < 4; c++) acc[r][c] = 0.f;

    for (int kk = 0; kk < FIN; kk += 16) {
#pragma unroll
        for (int r = 0; r < 4; r++) {
            int e = tid + r*256;
            int i = e >> 4, k = e & 15;
            float va = 0.f, vb = 0.f;
            if (kk + k < FIN) {
                va = xc[(size_t)(bi*64 + i)*FIN + kk + k];
                vb = xc[(size_t)(bj*64 + i)*FIN + kk + k];
            }
            As[k][i] = va; Bs[k][i] = vb;
        }
        __syncthreads();
#pragma unroll
        for (int k = 0; k < 16; k++) {
            float a[4], bbv[4];
#pragma unroll
            for (int r = 0; r < 4; r++) a[r] = As[k][ty*4+r];
#pragma unroll
            for (int c = 0; c < 4; c++) bbv[c] = Bs[k][tx*4+c];
#pragma unroll
            for (int r = 0; r < 4; r++)
#pragma unroll
                for (int c = 0; c < 4; c++) acc[r][c] = fmaf(a[r], bbv[c], acc[r][c]);
        }
        __syncthreads();
    }
    unsigned char* Ab = g_A + (size_t)b*NNODE*NNODE;
    const float* db = g_d + b*NNODE;
#pragma unroll
    for (int r = 0; r < 4; r++) {
        int gi = bi*64 + ty*4 + r;
        float di = db[gi];
#pragma unroll
        for (int c = 0; c < 4; c++) {
            int gj = bj*64 + tx*4 + c;
            unsigned char a = (acc[r][c] > 0.5f * di * db[gj]) ? (unsigned char)1 : (unsigned char)0;
            Ab[(size_t)gi*NNODE + gj] = a;
            Ab[(size_t)gj*NNODE + gi] = a;
        }
    }
}

// ---------------- 3) compact adjacency rows to neighbor lists (warp/row) ----------------
__global__ void k_compact(const unsigned char* __restrict__ A, unsigned short* __restrict__ nbr,
                          int* __restrict__ deg, int Nn, int rows) {
    int warp = (blockIdx.x * blockDim.x + threadIdx.x) >> 5;
    int lane = threadIdx.x & 31;
    if (warp >= rows) return;
    const unsigned char* ar = A + (size_t)warp*Nn;
    unsigned short* nr = nbr + (size_t)warp*Nn;
    int cnt = 0;
    for (int base = 0; base < Nn; base += 32) {
        unsigned char a = ar[base + lane];
        unsigned mask = __ballot_sync(0xffffffffu, a != 0);
        if (a) nr[cnt + __popc(mask & ((1u << lane) - 1u))] = (unsigned short)(base + lane);
        cnt += __popc(mask);
    }
    if (lane == 0) deg[warp] = cnt;
}

// ---------------- 4) mean aggregation via neighbor lists ----------------
__global__ void k_agg(const float* __restrict__ x, const unsigned short* __restrict__ nbr,
                      const int* __restrict__ deg, float* __restrict__ out, int Nn, int F_) {
    int row = blockIdx.x;            // b*Nn + n
    int t = threadIdx.x;
    if (t >= F_) return;
    int b = row / Nn;
    int dg = deg[row];
    const unsigned short* nr = nbr + (size_t)row*Nn;
    float acc = 0.f;
    for (int c = 0; c < dg; c++) {
        int m = nr[c];
        acc += x[((size_t)b*Nn + m)*F_ + t];
    }
    out[(size_t)row*F_ + t] = acc / fmaxf((float)dg, 1.f);
}

// ---------------- 5) SAGE linear: relu(agg*Wl^T + x*Wr^T + b) ----------------
__global__ void k_sage_gemm(const float* __restrict__ Ain, const float* __restrict__ Xin,
                            const float* __restrict__ Wl, const float* __restrict__ Wr,
                            const float* __restrict__ bias, float* __restrict__ Out,
                            int K, int Nout) {
    __shared__ float As[16][68];
    __shared__ float Bs[16][68];
    int bx = blockIdx.x, by = blockIdx.y;
    int tid = threadIdx.x;
    int tx = tid & 15, ty = tid >> 4;
    float acc[4][4];
#pragma unroll
    for (int r = 0; r < 4; r++)
#pragma unroll
        for (int c = 0; c < 4; c++) acc[r][c] = 0.f;

    for (int pass = 0; pass < 2; pass++) {
        const float* Am = pass ? Xin : Ain;
        const float* W  = pass ? Wr  : Wl;
        for (int kk = 0; kk < K; kk += 16) {
#pragma unroll
            for (int r = 0; r < 4; r++) {
                int e = tid + r*256;
                int i = e >> 4, k = e & 15;
                float va = 0.f, vb = 0.f;
                if (kk + k < K) {
                    va = Am[(size_t)(bx*64 + i)*K + kk + k];
                    vb = W[(size_t)(by*64 + i)*K + kk + k];
                }
                As[k][i] = va; Bs[k][i] = vb;
            }
            __syncthreads();
#pragma unroll
            for (int k = 0; k < 16; k++) {
                float a[4], bbv[4];
#pragma unroll
                for (int r = 0; r < 4; r++) a[r] = As[k][ty*4+r];
#pragma unroll
                for (int c = 0; c < 4; c++) bbv[c] = Bs[k][tx*4+c];
#pragma unroll
                for (int r = 0; r < 4; r++)
#pragma unroll
                    for (int c = 0; c < 4; c++) acc[r][c] = fmaf(a[r], bbv[c], acc[r][c]);
            }
            __syncthreads();
        }
    }
#pragma unroll
    for (int r = 0; r < 4; r++) {
        int gi = bx*64 + ty*4 + r;
#pragma unroll
        for (int c = 0; c < 4; c++) {
            int gj = by*64 + tx*4 + c;
            float v = acc[r][c] + bias[gj];
            Out[(size_t)gi*Nout + gj] = fmaxf(v, 0.f);
        }
    }
}

// ---------------- 6) pooling score precompute: srel = h.Wrel, sroot = h.Wroot ----------------
__global__ void k_score_pre(const float* __restrict__ h, const float* __restrict__ Wrel,
                            const float* __restrict__ Wroot, float* __restrict__ srel,
                            float* __restrict__ sroot, int F_, int rows) {
    int warp = (blockIdx.x * blockDim.x + threadIdx.x) >> 5;
    int lane = threadIdx.x & 31;
    if (warp >= rows) return;
    const float* hr = h + (size_t)warp*F_;
    float a = 0.f, r = 0.f;
    for (int f = lane; f < F_; f += 32) {
        float v = hr[f];
        a = fmaf(v, Wrel[f], a);
        r = fmaf(v, Wroot[f], r);
    }
    for (int o = 16; o; o >>= 1) {
        a += __shfl_down_sync(0xffffffffu, a, o);
        r += __shfl_down_sync(0xffffffffu, r, o);
    }
    if (lane == 0) { srel[warp] = a; sroot[warp] = r; }
}

// ---------------- 7) score = sum_{m in N(n)} srel[m] + brel + sroot[n] ----------------
__global__ void k_score_agg(const float* __restrict__ srel, const float* __restrict__ sroot,
                            const unsigned short* __restrict__ nbr, const int* __restrict__ deg,
                            const float* __restrict__ brel, float* __restrict__ score,
                            int Nn, int rows) {
    int warp = (blockIdx.x * blockDim.x + threadIdx.x) >> 5;
    int lane = threadIdx.x & 31;
    if (warp >= rows) return;
    int b = warp / Nn;
    int dg = deg[warp];
    const unsigned short* nr = nbr + (size_t)warp*Nn;
    float a = 0.f;
    for (int c = lane; c < dg; c += 32) a += srel[b*Nn + nr[c]];
    for (int o = 16; o; o >>= 1) a += __shfl_down_sync(0xffffffffu, a, o);
    if (lane == 0) score[warp] = a + brel[0] + sroot[warp];
}

// ---------------- bitonic sort helpers (descending by score, tie -> smaller idx) ----------------
__device__ __forceinline__ bool prec_cmp(float sa, int ia, float sb, int ib) {
    return (sa > sb) || (sa == sb && ia < ib);
}

template<int NSORT>
__device__ void bitonic_sort(float* s, int* id, int t) {
    for (int k = 2; k <= NSORT; k <<= 1) {
        for (int j = k >> 1; j > 0; j >>= 1) {
            int ixj = t ^ j;
            if (ixj > t) {
                float s1 = s[t], s2 = s[ixj];
                int   i1 = id[t], i2 = id[ixj];
                bool sw;
                if ((t & k) == 0) sw = prec_cmp(s2, i2, s1, i1);
                else              sw = prec_cmp(s1, i1, s2, i2);
                if (sw) { s[t] = s2; s[ixj] = s1; id[t] = i2; id[ixj] = i1; }
            }
            __syncthreads();
        }
    }
}

// ---------------- 8) top-k pool1: sort 1024, take 512, gather x1 = h1[idx]*tanh(s) ----------------
__global__ void k_topk1(const float* __restrict__ score) {
    __shared__ float s[NNODE];
    __shared__ int   id[NNODE];
    int b = blockIdx.x, t = threadIdx.x;   // 1024 threads
    s[t] = score[b*NNODE + t];
    id[t] = t;
    __syncthreads();
    bitonic_sort<NNODE>(s, id, t);
    if (t < KK1) {
        g_idx1[b*KK1 + t] = id[t];
        s[t] = tanhf(s[t]);
    }
    __syncthreads();
    const float* h1b = g_h1 + (size_t)b*NNODE*HH;
    float* x1b = g_x1 + (size_t)b*KK1*HH;
    for (int e = t; e < KK1*HH; e += NNODE) {
        int k = e >> 7;           // /HH
        int f = e & 127;
        x1b[e] = h1b[(size_t)id[k]*HH + f] * s[k];
    }
}

// ---------------- 9) gather A1 = A[idx][:,idx] ----------------
__global__ void k_gatherA() {
    int b = blockIdx.y, i = blockIdx.x, t = threadIdx.x;   // 256 threads
    __shared__ int sidx[KK1];
    for (int e = t; e < KK1; e += 256) sidx[e] = g_idx1[b*KK1 + e];
    __syncthreads();
    const unsigned char* ar = g_A + ((size_t)b*NNODE + sidx[i])*NNODE;
    unsigned char* o = g_A1 + ((size_t)b*KK1 + i)*KK1;
    for (int j = t; j < KK1; j += 256) o[j] = ar[sidx[j]];
}

// ---------------- 10) top-k pool2: sort 512, take 256 (idx + tanh only) ----------------
__global__ void k_topk2(const float* __restrict__ score) {
    __shared__ float s[KK1];
    __shared__ int   id[KK1];
    int b = blockIdx.x, t = threadIdx.x;   // 512 threads
    s[t] = score[b*KK1 + t];
    id[t] = t;
    __syncthreads();
    bitonic_sort<KK1>(s, id, t);
    if (t < KK2) {
        g_idx2[b*KK2 + t] = id[t];
        g_tanh2[b*KK2 + t] = tanhf(s[t]);
    }
}

// ---------------- 11) gather + scale + global mean pool -> [B,64] ----------------
__global__ void k_pool_mean() {
    int b = blockIdx.x, f = threadIdx.x;   // 64 threads
    const float* h2b = g_h2 + (size_t)b*KK1*OO;
    float acc = 0.f;
    for (int k = 0; k < KK2; k++)
        acc += h2b[(size_t)g_idx2[b*KK2 + k]*OO + f] * g_tanh2[b*KK2 + k];
    g_pool[b*OO + f] = acc * (1.f/KK2);
}

// ---------------- 12) MLP head: fc1->relu->bn1, fc2->relu->bn2, fc3, softmax ----------------
__global__ void k_mlp(const float* __restrict__ fc1_w, const float* __restrict__ fc1_b,
                      const float* __restrict__ g1, const float* __restrict__ b1,
                      const float* __restrict__ m1, const float* __restrict__ v1,
                      const float* __restrict__ fc2_w, const float* __restrict__ fc2_b,
                      const float* __restrict__ g2, const float* __restrict__ b2,
                      const float* __restrict__ m2, const float* __restrict__ v2,
                      const float* __restrict__ fc3_w, const float* __restrict__ fc3_b,
                      float* __restrict__ out) {
    int b = blockIdx.x, t = threadIdx.x;   // 512 threads
    __shared__ float sin[OO];
    __shared__ float a1[512];
    __shared__ float a2[256];
    __shared__ float lg[2];
    if (t < OO) sin[t] = g_pool[b*OO + t];
    __syncthreads();
    {
        float acc = fc1_b[t];
        const float* w = fc1_w + (size_t)t*OO;
        for (int k = 0; k < OO; k++) acc = fmaf(sin[k], w[k], acc);
        acc = fmaxf(acc, 0.f);
        a1[t] = g1[t] * (acc - m1[t]) * rsqrtf(v1[t] + 1e-5f) + b1[t];
    }
    __syncthreads();
    if (t < 256) {
        float acc = fc2_b[t];
        const float* w = fc2_w + (size_t)t*512;
        for (int k = 0; k < 512; k++) acc = fmaf(a1[k], w[k], acc);
        acc = fmaxf(acc, 0.f);
        a2[t] = g2[t] * (acc - m2[t]) * rsqrtf(v2[t] + 1e-5f) + b2[t];
    }
    __syncthreads();
    if (t < 2) {
        float acc = fc3_b[t];
        const float* w = fc3_w + (size_t)t*256;
        for (int k = 0; k < 256; k++) acc = fmaf(a2[k], w[k], acc);
        lg[t] = acc;
    }
    __syncthreads();
    if (t == 0) {
        float m = fmaxf(lg[0], lg[1]);
        float e0 = expf(lg[0] - m), e1 = expf(lg[1] - m);
        float inv = 1.f / (e0 + e1);
        out[b*2 + 0] = e0 * inv;
        out[b*2 + 1] = e1 * inv;
    }
}

// ---------------- launch ----------------
template <typename T>
static T* sym_addr(const void* symbol) {
    void* p = nullptr;
    cudaGetSymbolAddress(&p, symbol);
    return (T*)p;
}

extern "C" void kernel_launch(void* const* d_in, const int* in_sizes, int n_in,
                              void* d_out, int out_size) {
    const float* input   = (const float*)d_in[0];
    const float* W1l     = (const float*)d_in[1];
    const float* b1l     = (const float*)d_in[2];
    const float* W1r     = (const float*)d_in[3];
    const float* Wp1_rel = (const float*)d_in[4];
    const float* bp1_rel = (const float*)d_in[5];
    const float* Wp1_root= (const float*)d_in[6];
    const float* W2l     = (const float*)d_in[7];
    const float* b2l     = (const float*)d_in[8];
    const float* W2r     = (const float*)d_in[9];
    const float* Wp2_rel = (const float*)d_in[10];
    const float* bp2_rel = (const float*)d_in[11];
    const float* Wp2_root= (const float*)d_in[12];
    const float* fc1_w   = (const float*)d_in[13];
    const float* fc1_b   = (const float*)d_in[14];
    const float* bn1_g   = (const float*)d_in[15];
    const float* bn1_b   = (const float*)d_in[16];
    const float* bn1_m   = (const float*)d_in[17];
    const float* bn1_v   = (const float*)d_in[18];
    const float* fc2_w   = (const float*)d_in[19];
    const float* fc2_b   = (const float*)d_in[20];
    const float* bn2_g   = (const float*)d_in[21];
    const float* bn2_b   = (const float*)d_in[22];
    const float* bn2_m   = (const float*)d_in[23];
    const float* bn2_v   = (const float*)d_in[24];
    const float* fc3_w   = (const float*)d_in[25];
    const float* fc3_b   = (const float*)d_in[26];
    float* out = (float*)d_out;

    unsigned char*  pA    = sym_addr<unsigned char>(g_A);
    unsigned short* pNbr  = sym_addr<unsigned short>(g_nbr);
    int*            pDeg  = sym_addr<int>(g_deg);
    float*          pAgg1 = sym_addr<float>(g_agg1);
    float*          pH1   = sym_addr<float>(g_h1);
    float*          pSrel = sym_addr<float>(g_srel);
    float*          pSroot= sym_addr<float>(g_sroot);
    float*          pScore= sym_addr<float>(g_score);
    float*          pX1   = sym_addr<float>(g_x1);
    unsigned char*  pA1   = sym_addr<unsigned char>(g_A1);
    unsigned short* pNbr2 = sym_addr<unsigned short>(g_nbr2);
    int*            pDeg2 = sym_addr<int>(g_deg2);
    float*          pAgg2 = sym_addr<float>(g_agg2);
    float*          pH2   = sym_addr<float>(g_h2);
    float*          pSrel2= sym_addr<float>(g_srel2);
    float*          pSroot2=sym_addr<float>(g_sroot2);
    float*          pScore2=sym_addr<float>(g_score2);

    // Stage 0: correlation adjacency
    k_center<<<BB*NNODE, 256>>>(input);
    dim3 gcov(NNODE/64, NNODE/64, BB);
    k_cov<<<gcov, 256>>>();
    k_compact<<<(BB*NNODE*32 + 255)/256, 256>>>(pA, pNbr, pDeg, NNODE, BB*NNODE);

    // Stage 1: SAGEConv1 + relu
    k_agg<<<BB*NNODE, 256>>>(input, pNbr, pDeg, pAgg1, NNODE, FIN);
    k_sage_gemm<<<dim3(BB*NNODE/64, HH/64), 256>>>(pAgg1, input, W1l, W1r, b1l, pH1, FIN, HH);

    // Stage 2: SAGPool1
    k_score_pre<<<(BB*NNODE*32 + 255)/256, 256>>>(pH1, Wp1_rel, Wp1_root, pSrel, pSroot, HH, BB*NNODE);
    k_score_agg<<<(BB*NNODE*32 + 255)/256, 256>>>(pSrel, pSroot, pNbr, pDeg, bp1_rel, pScore, NNODE, BB*NNODE);
    k_topk1<<<BB, NNODE>>>(pScore);
    k_gatherA<<<dim3(KK1, BB), 256>>>();
    k_compact<<<(BB*KK1*32 + 255)/256, 256>>>(pA1, pNbr2, pDeg2, KK1, BB*KK1);

    // Stage 3: SAGEConv2 + relu
    k_agg<<<BB*KK1, 128>>>(pX1, pNbr2, pDeg2, pAgg2, KK1, HH);
    k_sage_gemm<<<dim3(BB*KK1/64, OO/64), 256>>>(pAgg2, pX1, W2l, W2r, b2l, pH2, HH, OO);

    // Stage 4: SAGPool2 + global mean pool
    k_score_pre<<<(BB*KK1*32 + 255)/256, 256>>>(pH2, Wp2_rel, Wp2_root, pSrel2, pSroot2, OO, BB*KK1);
    k_score_agg<<<(BB*KK1*32 + 255)/256, 256>>>(pSrel2, pSroot2, pNbr2, pDeg2, bp2_rel, pScore2, KK1, BB*KK1);
    k_topk2<<<BB, KK1>>>(pScore2);
    k_pool_mean<<<BB, OO>>>();

    // Stage 5: MLP head + softmax
    k_mlp<<<BB, 512>>>(fc1_w, fc1_b, bn1_g, bn1_b, bn1_m, bn1_v,
                       fc2_w, fc2_b, bn2_g, bn2_b, bn2_m, bn2_v,
                       fc3_w, fc3_b, out);
}

// round 6
// speedup vs baseline: 1.0990x; 1.0990x over previous
#include <cuda_runtime.h>
#include <cuda_bf16.h>
#include <mma.h>
#include <math.h>

using namespace nvcuda;

#define BB    64
#define NNODE 1024
#define FIN   195
#define HH    128
#define OO    64
#define KK1   512
#define KK2   256
#define COVK  256   // K=195 zero-padded to 256 for clean 16-step MMA

// ---------------- scratch (device globals; no allocation allowed) ----------------
__device__ __nv_bfloat16  g_ybf[(size_t)BB*NNODE*COVK];   // normalized rows, bf16, zero-padded
__device__ unsigned char  g_A[(size_t)BB*NNODE*NNODE];
__device__ unsigned short g_nbr[(size_t)BB*NNODE*NNODE];
__device__ int            g_deg[BB*NNODE];
__device__ float          g_agg1[(size_t)BB*NNODE*FIN];
__device__ float          g_h1[(size_t)BB*NNODE*HH];
__device__ float          g_srel[BB*NNODE];
__device__ float          g_sroot[BB*NNODE];
__device__ float          g_score[BB*NNODE];
__device__ int            g_idx1[BB*KK1];
__device__ float          g_x1[(size_t)BB*KK1*HH];
__device__ unsigned short g_nbr2[(size_t)BB*KK1*KK1];
__device__ int            g_deg2[BB*KK1];
__device__ float          g_agg2[(size_t)BB*KK1*HH];
__device__ float          g_h2[(size_t)BB*KK1*OO];
__device__ float          g_srel2[BB*KK1];
__device__ float          g_sroot2[BB*KK1];
__device__ float          g_score2[BB*KK1];
__device__ int            g_idx2[BB*KK2];
__device__ float          g_tanh2[BB*KK2];
__device__ float          g_pool[BB*OO];

// ---------------- 1) center + normalize rows -> bf16 y (warp per row) ----------------
__global__ void k_center_norm(const float* __restrict__ x) {
    int row = blockIdx.x * 8 + (threadIdx.x >> 5);
    int lane = threadIdx.x & 31;
    const float* xr = x + (size_t)row * FIN;
    float v[7];
    float sum = 0.f;
#pragma unroll
    for (int j = 0; j < 7; j++) {
        int f = lane + 32 * j;
        v[j] = (f < FIN) ? xr[f] : 0.f;
        sum += v[j];
    }
#pragma unroll
    for (int o = 16; o; o >>= 1) sum += __shfl_xor_sync(0xffffffffu, sum, o);
    float mean = sum * (1.0f / FIN);
    float ssq = 0.f;
#pragma unroll
    for (int j = 0; j < 7; j++) {
        int f = lane + 32 * j;
        float c = (f < FIN) ? (v[j] - mean) : 0.f;
        v[j] = c;
        ssq += c * c;
    }
#pragma unroll
    for (int o = 16; o; o >>= 1) ssq += __shfl_xor_sync(0xffffffffu, ssq, o);
    float rinv = rsqrtf(fmaxf(ssq, 1e-12f));
    __nv_bfloat16* yr = g_ybf + (size_t)row * COVK;
#pragma unroll
    for (int j = 0; j < 8; j++) {
        int f = lane + 32 * j;
        float val = (j < 7 && f < FIN) ? v[j] * rinv : 0.f;
        yr[f] = __float2bfloat16(val);
    }
}

// ---------------- 2) cov via wmma bf16 HMMA: A = (y.y^T > 0.5) ----------------
// CTA: 128x128 output tile, 8 warps in 2x4 grid, warp tile 64x32.
// smem: As/Bs bf16 128x264 (pad to dodge conflicts); D reuses As as f32 128x132.
#define COV_LDM 264
#define COV_TILE_BF (128 * COV_LDM)               // bf16 elems (67584 B)
#define COV_SMEM_TOTAL (2 * COV_TILE_BF * 2)      // 135168 B

__global__ void __launch_bounds__(256, 1) k_cov_wmma(const __nv_bfloat16* __restrict__ y,
                                                     unsigned char* __restrict__ Aout) {
    extern __shared__ __nv_bfloat16 smem[];
    __nv_bfloat16* Asb = smem;
    __nv_bfloat16* Bsb = smem + COV_TILE_BF;
    int b = blockIdx.z, bi = blockIdx.x, bj = blockIdx.y;
    if (bj < bi) return;
    int tid = threadIdx.x;
    int w = tid >> 5;
    int wr = w >> 2, wc = w & 3;          // 2 x 4 warp grid

    // stage both 128x256 bf16 tiles into smem (16B vector copies)
    const uint4* yb = (const uint4*)(y + (size_t)b * NNODE * COVK);
#pragma unroll
    for (int half = 0; half < 2; half++) {
        int rowoff = (half ? bj : bi) * 128;
        __nv_bfloat16* dst = half ? Bsb : Asb;
        const uint4* src = yb + (size_t)rowoff * (COVK / 8);
        for (int e = tid; e < 128 * 32; e += 256) {
            int r = e >> 5, q = e & 31;
            *(uint4*)(dst + r * COV_LDM + q * 8) = src[r * 32 + q];
        }
    }
    __syncthreads();

    wmma::fragment<wmma::accumulator, 16, 16, 16, float> acc[4][2];
#pragma unroll
    for (int i = 0; i < 4; i++)
#pragma unroll
        for (int j = 0; j < 2; j++) wmma::fill_fragment(acc[i][j], 0.f);

    for (int k0 = 0; k0 < COVK; k0 += 16) {
        wmma::fragment<wmma::matrix_a, 16, 16, 16, __nv_bfloat16, wmma::row_major> af[4];
        wmma::fragment<wmma::matrix_b, 16, 16, 16, __nv_bfloat16, wmma::col_major> bf[2];
#pragma unroll
        for (int i = 0; i < 4; i++)
            wmma::load_matrix_sync(af[i], Asb + (wr * 64 + i * 16) * COV_LDM + k0, COV_LDM);
#pragma unroll
        for (int j = 0; j < 2; j++)
            wmma::load_matrix_sync(bf[j], Bsb + (wc * 32 + j * 16) * COV_LDM + k0, COV_LDM);
#pragma unroll
        for (int i = 0; i < 4; i++)
#pragma unroll
            for (int j = 0; j < 2; j++)
                wmma::mma_sync(acc[i][j], af[i], bf[j], acc[i][j]);
    }
    __syncthreads();   // done reading As; reuse as f32 D buffer

    float* Ds = (float*)Asb;               // 128 x 132 f32
#pragma unroll
    for (int i = 0; i < 4; i++)
#pragma unroll
        for (int j = 0; j < 2; j++)
            wmma::store_matrix_sync(Ds + (wr * 64 + i * 16) * 132 + wc * 32 + j * 16,
                                    acc[i][j], 132, wmma::mem_row_major);
    __syncthreads();

    // threshold + write A block (and transposed block for bi != bj)
    int r = tid >> 1;               // 0..127
    int ch = (tid & 1) * 64;        // column half
    {
        unsigned char* arow = Aout + ((size_t)b * NNODE + bi * 128 + r) * NNODE + bj * 128 + ch;
#pragma unroll
        for (int g = 0; g < 16; g++) {
            unsigned wv = 0;
#pragma unroll
            for (int k2 = 0; k2 < 4; k2++)
                wv |= (Ds[r * 132 + ch + g * 4 + k2] > 0.5f) ? (1u << (8 * k2)) : 0u;
            *(unsigned*)(arow + g * 4) = wv;
        }
    }
    if (bi != bj) {
        unsigned char* arow = Aout + ((size_t)b * NNODE + bj * 128 + r) * NNODE + bi * 128 + ch;
#pragma unroll
        for (int g = 0; g < 16; g++) {
            unsigned wv = 0;
#pragma unroll
            for (int k2 = 0; k2 < 4; k2++)
                wv |= (Ds[(ch + g * 4 + k2) * 132 + r] > 0.5f) ? (1u << (8 * k2)) : 0u;
            *(unsigned*)(arow + g * 4) = wv;
        }
    }
}

// ---------------- 3) compact adjacency rows to neighbor lists (warp/row) ----------------
__global__ void k_compact(const unsigned char* __restrict__ A, unsigned short* __restrict__ nbr,
                          int* __restrict__ deg, int Nn, int rows) {
    int warp = (blockIdx.x * blockDim.x + threadIdx.x) >> 5;
    int lane = threadIdx.x & 31;
    if (warp >= rows) return;
    const unsigned char* ar = A + (size_t)warp * Nn;
    unsigned short* nr = nbr + (size_t)warp * Nn;
    int cnt = 0;
    for (int base = 0; base < Nn; base += 32) {
        unsigned char a = ar[base + lane];
        unsigned mask = __ballot_sync(0xffffffffu, a != 0);
        if (a) nr[cnt + __popc(mask & ((1u << lane) - 1u))] = (unsigned short)(base + lane);
        cnt += __popc(mask);
    }
    if (lane == 0) deg[warp] = cnt;
}

// ---------------- 4) mean aggregation, warp per row, register-resident features ----------------
template <int NJ>
__global__ void k_agg_w(const float* __restrict__ x, const unsigned short* __restrict__ nbr,
                        const int* __restrict__ deg, float* __restrict__ out, int Nn, int F_) {
    int row = blockIdx.x * 8 + (threadIdx.x >> 5);
    int lane = threadIdx.x & 31;
    int b = row / Nn;
    int dg = deg[row];
    const unsigned short* nr = nbr + (size_t)row * Nn;
    float acc[NJ];
#pragma unroll
    for (int j = 0; j < NJ; j++) acc[j] = 0.f;
    for (int c = 0; c < dg; c++) {
        const float* xr = x + ((size_t)b * Nn + nr[c]) * F_;
#pragma unroll
        for (int j = 0; j < NJ; j++) {
            int f = lane + 32 * j;
            if (f < F_) acc[j] += xr[f];
        }
    }
    float inv = 1.f / fmaxf((float)dg, 1.f);
    float* orow = out + (size_t)row * F_;
#pragma unroll
    for (int j = 0; j < NJ; j++) {
        int f = lane + 32 * j;
        if (f < F_) orow[f] = acc[j] * inv;
    }
}

// ---------------- 5a) SAGE linear 128x128 tile, 8x8 per-thread microtile (stage 1) ----------------
__global__ void __launch_bounds__(256) k_sage_gemm128(
        const float* __restrict__ Ain, const float* __restrict__ Xin,
        const float* __restrict__ Wl, const float* __restrict__ Wr,
        const float* __restrict__ bias, float* __restrict__ Out, int K, int Nout) {
    __shared__ float As[8][136];
    __shared__ float Bs[8][136];
    int bx = blockIdx.x;
    int tid = threadIdx.x, tx = tid & 15, ty = tid >> 4;
    float acc[8][8];
#pragma unroll
    for (int r = 0; r < 8; r++)
#pragma unroll
        for (int c = 0; c < 8; c++) acc[r][c] = 0.f;

    for (int pass = 0; pass < 2; pass++) {
        const float* Am = pass ? Xin : Ain;
        const float* W  = pass ? Wr  : Wl;
        for (int kk = 0; kk < K; kk += 8) {
#pragma unroll
            for (int r = 0; r < 4; r++) {
                int e = tid + r * 256;
                int i = e >> 3, k = e & 7;
                float va = 0.f, vb = 0.f;
                if (kk + k < K) {
                    va = Am[(size_t)(bx * 128 + i) * K + kk + k];
                    vb = W[(size_t)i * K + kk + k];
                }
                As[k][i] = va; Bs[k][i] = vb;
            }
            __syncthreads();
#pragma unroll
            for (int k = 0; k < 8; k++) {
                float a[8], bv[8];
#pragma unroll
                for (int r = 0; r < 8; r++) a[r] = As[k][ty * 8 + r];
#pragma unroll
                for (int c = 0; c < 8; c++) bv[c] = Bs[k][tx * 8 + c];
#pragma unroll
                for (int r = 0; r < 8; r++)
#pragma unroll
                    for (int c = 0; c < 8; c++) acc[r][c] = fmaf(a[r], bv[c], acc[r][c]);
            }
            __syncthreads();
        }
    }
#pragma unroll
    for (int r = 0; r < 8; r++) {
        int gi = bx * 128 + ty * 8 + r;
#pragma unroll
        for (int c = 0; c < 8; c++) {
            int gj = tx * 8 + c;
            Out[(size_t)gi * Nout + gj] = fmaxf(acc[r][c] + bias[gj], 0.f);
        }
    }
}

// ---------------- 5b) SAGE linear 64x64 tile (stage 2) ----------------
__global__ void k_sage_gemm(const float* __restrict__ Ain, const float* __restrict__ Xin,
                            const float* __restrict__ Wl, const float* __restrict__ Wr,
                            const float* __restrict__ bias, float* __restrict__ Out,
                            int K, int Nout) {
    __shared__ float As[16][68];
    __shared__ float Bs[16][68];
    int bx = blockIdx.x, by = blockIdx.y;
    int tid = threadIdx.x;
    int tx = tid & 15, ty = tid >> 4;
    float acc[4][4];
#pragma unroll
    for (int r = 0; r < 4; r++)
#pragma unroll
        for (int c = 0; c < 4; c++) acc[r][c] = 0.f;

    for (int pass = 0; pass < 2; pass++) {
        const float* Am = pass ? Xin : Ain;
        const float* W  = pass ? Wr  : Wl;
        for (int kk = 0; kk < K; kk += 16) {
#pragma unroll
            for (int r = 0; r < 4; r++) {
                int e = tid + r * 256;
                int i = e >> 4, k = e & 15;
                float va = 0.f, vb = 0.f;
                if (kk + k < K) {
                    va = Am[(size_t)(bx * 64 + i) * K + kk + k];
                    vb = W[(size_t)(by * 64 + i) * K + kk + k];
                }
                As[k][i] = va; Bs[k][i] = vb;
            }
            __syncthreads();
#pragma unroll
            for (int k = 0; k < 16; k++) {
                float a[4], bbv[4];
#pragma unroll
                for (int r = 0; r < 4; r++) a[r] = As[k][ty * 4 + r];
#pragma unroll
                for (int c = 0; c < 4; c++) bbv[c] = Bs[k][tx * 4 + c];
#pragma unroll
                for (int r = 0; r < 4; r++)
#pragma unroll
                    for (int c = 0; c < 4; c++) acc[r][c] = fmaf(a[r], bbv[c], acc[r][c]);
            }
            __syncthreads();
        }
    }
#pragma unroll
    for (int r = 0; r < 4; r++) {
        int gi = bx * 64 + ty * 4 + r;
#pragma unroll
        for (int c = 0; c < 4; c++) {
            int gj = by * 64 + tx * 4 + c;
            float v = acc[r][c] + bias[gj];
            Out[(size_t)gi * Nout + gj] = fmaxf(v, 0.f);
        }
    }
}

// ---------------- 6) pooling score precompute ----------------
__global__ void k_score_pre(const float* __restrict__ h, const float* __restrict__ Wrel,
                            const float* __restrict__ Wroot, float* __restrict__ srel,
                            float* __restrict__ sroot, int F_, int rows) {
    int warp = (blockIdx.x * blockDim.x + threadIdx.x) >> 5;
    int lane = threadIdx.x & 31;
    if (warp >= rows) return;
    const float* hr = h + (size_t)warp * F_;
    float a = 0.f, r = 0.f;
    for (int f = lane; f < F_; f += 32) {
        float v = hr[f];
        a = fmaf(v, Wrel[f], a);
        r = fmaf(v, Wroot[f], r);
    }
    for (int o = 16; o; o >>= 1) {
        a += __shfl_down_sync(0xffffffffu, a, o);
        r += __shfl_down_sync(0xffffffffu, r, o);
    }
    if (lane == 0) { srel[warp] = a; sroot[warp] = r; }
}

// ---------------- 7) score aggregation ----------------
__global__ void k_score_agg(const float* __restrict__ srel, const float* __restrict__ sroot,
                            const unsigned short* __restrict__ nbr, const int* __restrict__ deg,
                            const float* __restrict__ brel, float* __restrict__ score,
                            int Nn, int rows) {
    int warp = (blockIdx.x * blockDim.x + threadIdx.x) >> 5;
    int lane = threadIdx.x & 31;
    if (warp >= rows) return;
    int b = warp / Nn;
    int dg = deg[warp];
    const unsigned short* nr = nbr + (size_t)warp * Nn;
    float a = 0.f;
    for (int c = lane; c < dg; c += 32) a += srel[b * Nn + nr[c]];
    for (int o = 16; o; o >>= 1) a += __shfl_down_sync(0xffffffffu, a, o);
    if (lane == 0) score[warp] = a + brel[0] + sroot[warp];
}

// ---------------- bitonic sort (descending, tie -> smaller idx) ----------------
__device__ __forceinline__ bool prec_cmp(float sa, int ia, float sb, int ib) {
    return (sa > sb) || (sa == sb && ia < ib);
}

template <int NSORT>
__device__ void bitonic_sort(float* s, int* id, int t) {
    for (int k = 2; k <= NSORT; k <<= 1) {
        for (int j = k >> 1; j > 0; j >>= 1) {
            int ixj = t ^ j;
            if (ixj > t) {
                float s1 = s[t], s2 = s[ixj];
                int   i1 = id[t], i2 = id[ixj];
                bool sw;
                if ((t & k) == 0) sw = prec_cmp(s2, i2, s1, i1);
                else              sw = prec_cmp(s1, i1, s2, i2);
                if (sw) { s[t] = s2; s[ixj] = s1; id[t] = i2; id[ixj] = i1; }
            }
            __syncthreads();
        }
    }
}

// ---------------- 8) top-k pool1 + gather x1 ----------------
__global__ void k_topk1(const float* __restrict__ score) {
    __shared__ float s[NNODE];
    __shared__ int   id[NNODE];
    int b = blockIdx.x, t = threadIdx.x;
    s[t] = score[b * NNODE + t];
    id[t] = t;
    __syncthreads();
    bitonic_sort<NNODE>(s, id, t);
    if (t < KK1) {
        g_idx1[b * KK1 + t] = id[t];
        s[t] = tanhf(s[t]);
    }
    __syncthreads();
    const float* h1b = g_h1 + (size_t)b * NNODE * HH;
    float* x1b = g_x1 + (size_t)b * KK1 * HH;
    for (int e = t; e < KK1 * HH; e += NNODE) {
        int k = e >> 7;
        int f = e & 127;
        x1b[e] = h1b[(size_t)id[k] * HH + f] * s[k];
    }
}

// ---------------- 9) fused: nbr2/deg2 directly from A + idx1 (no dense A1) ----------------
__global__ void k_nbr2() {
    int b = blockIdx.y;
    int wid = threadIdx.x >> 5, lane = threadIdx.x & 31;
    int i = blockIdx.x * 8 + wid;
    __shared__ int sidx[KK1];
    for (int e = threadIdx.x; e < KK1; e += 256) sidx[e] = g_idx1[b * KK1 + e];
    __syncthreads();
    const unsigned char* ar = g_A + ((size_t)b * NNODE + sidx[i]) * NNODE;
    unsigned short* nr = g_nbr2 + ((size_t)b * KK1 + i) * KK1;
    int cnt = 0;
    for (int base = 0; base < KK1; base += 32) {
        int jj = base + lane;
        unsigned char a = ar[sidx[jj]];
        unsigned mask = __ballot_sync(0xffffffffu, a != 0);
        if (a) nr[cnt + __popc(mask & ((1u << lane) - 1u))] = (unsigned short)jj;
        cnt += __popc(mask);
    }
    if (lane == 0) g_deg2[b * KK1 + i] = cnt;
}

// ---------------- 10) top-k pool2 ----------------
__global__ void k_topk2(const float* __restrict__ score) {
    __shared__ float s[KK1];
    __shared__ int   id[KK1];
    int b = blockIdx.x, t = threadIdx.x;
    s[t] = score[b * KK1 + t];
    id[t] = t;
    __syncthreads();
    bitonic_sort<KK1>(s, id, t);
    if (t < KK2) {
        g_idx2[b * KK2 + t] = id[t];
        g_tanh2[b * KK2 + t] = tanhf(s[t]);
    }
}

// ---------------- 11) gather + scale + global mean pool ----------------
__global__ void k_pool_mean() {
    int b = blockIdx.x, f = threadIdx.x;   // 64 threads
    const float* h2b = g_h2 + (size_t)b * KK1 * OO;
    float acc = 0.f;
    for (int k = 0; k < KK2; k++)
        acc += h2b[(size_t)g_idx2[b * KK2 + k] * OO + f] * g_tanh2[b * KK2 + k];
    g_pool[b * OO + f] = acc * (1.f / KK2);
}

// ---------------- 12) MLP head ----------------
__global__ void k_mlp(const float* __restrict__ fc1_w, const float* __restrict__ fc1_b,
                      const float* __restrict__ g1, const float* __restrict__ b1,
                      const float* __restrict__ m1, const float* __restrict__ v1,
                      const float* __restrict__ fc2_w, const float* __restrict__ fc2_b,
                      const float* __restrict__ g2, const float* __restrict__ b2,
                      const float* __restrict__ m2, const float* __restrict__ v2,
                      const float* __restrict__ fc3_w, const float* __restrict__ fc3_b,
                      float* __restrict__ out) {
    int b = blockIdx.x, t = threadIdx.x;   // 512 threads
    __shared__ float sin[OO];
    __shared__ float a1[512];
    __shared__ float a2[256];
    __shared__ float lg[2];
    if (t < OO) sin[t] = g_pool[b * OO + t];
    __syncthreads();
    {
        float acc = fc1_b[t];
        const float* w = fc1_w + (size_t)t * OO;
        for (int k = 0; k < OO; k++) acc = fmaf(sin[k], w[k], acc);
        acc = fmaxf(acc, 0.f);
        a1[t] = g1[t] * (acc - m1[t]) * rsqrtf(v1[t] + 1e-5f) + b1[t];
    }
    __syncthreads();
    if (t < 256) {
        float acc = fc2_b[t];
        const float* w = fc2_w + (size_t)t * 512;
        for (int k = 0; k < 512; k++) acc = fmaf(a1[k], w[k], acc);
        acc = fmaxf(acc, 0.f);
        a2[t] = g2[t] * (acc - m2[t]) * rsqrtf(v2[t] + 1e-5f) + b2[t];
    }
    __syncthreads();
    if (t < 2) {
        float acc = fc3_b[t];
        const float* w = fc3_w + (size_t)t * 256;
        for (int k = 0; k < 256; k++) acc = fmaf(a2[k], w[k], acc);
        lg[t] = acc;
    }
    __syncthreads();
    if (t == 0) {
        float m = fmaxf(lg[0], lg[1]);
        float e0 = expf(lg[0] - m), e1 = expf(lg[1] - m);
        float inv = 1.f / (e0 + e1);
        out[b * 2 + 0] = e0 * inv;
        out[b * 2 + 1] = e1 * inv;
    }
}

// ---------------- launch ----------------
template <typename T>
static T* sym_addr(const void* symbol) {
    void* p = nullptr;
    cudaGetSymbolAddress(&p, symbol);
    return (T*)p;
}

extern "C" void kernel_launch(void* const* d_in, const int* in_sizes, int n_in,
                              void* d_out, int out_size) {
    const float* input   = (const float*)d_in[0];
    const float* W1l     = (const float*)d_in[1];
    const float* b1l     = (const float*)d_in[2];
    const float* W1r     = (const float*)d_in[3];
    const float* Wp1_rel = (const float*)d_in[4];
    const float* bp1_rel = (const float*)d_in[5];
    const float* Wp1_root= (const float*)d_in[6];
    const float* W2l     = (const float*)d_in[7];
    const float* b2l     = (const float*)d_in[8];
    const float* W2r     = (const float*)d_in[9];
    const float* Wp2_rel = (const float*)d_in[10];
    const float* bp2_rel = (const float*)d_in[11];
    const float* Wp2_root= (const float*)d_in[12];
    const float* fc1_w   = (const float*)d_in[13];
    const float* fc1_b   = (const float*)d_in[14];
    const float* bn1_g   = (const float*)d_in[15];
    const float* bn1_b   = (const float*)d_in[16];
    const float* bn1_m   = (const float*)d_in[17];
    const float* bn1_v   = (const float*)d_in[18];
    const float* fc2_w   = (const float*)d_in[19];
    const float* fc2_b   = (const float*)d_in[20];
    const float* bn2_g   = (const float*)d_in[21];
    const float* bn2_b   = (const float*)d_in[22];
    const float* bn2_m   = (const float*)d_in[23];
    const float* bn2_v   = (const float*)d_in[24];
    const float* fc3_w   = (const float*)d_in[25];
    const float* fc3_b   = (const float*)d_in[26];
    float* out = (float*)d_out;

    __nv_bfloat16*  pY    = sym_addr<__nv_bfloat16>(g_ybf);
    unsigned char*  pA    = sym_addr<unsigned char>(g_A);
    unsigned short* pNbr  = sym_addr<unsigned short>(g_nbr);
    int*            pDeg  = sym_addr<int>(g_deg);
    float*          pAgg1 = sym_addr<float>(g_agg1);
    float*          pH1   = sym_addr<float>(g_h1);
    float*          pSrel = sym_addr<float>(g_srel);
    float*          pSroot= sym_addr<float>(g_sroot);
    float*          pScore= sym_addr<float>(g_score);
    float*          pX1   = sym_addr<float>(g_x1);
    unsigned short* pNbr2 = sym_addr<unsigned short>(g_nbr2);
    int*            pDeg2 = sym_addr<int>(g_deg2);
    float*          pAgg2 = sym_addr<float>(g_agg2);
    float*          pH2   = sym_addr<float>(g_h2);
    float*          pSrel2= sym_addr<float>(g_srel2);
    float*          pSroot2=sym_addr<float>(g_sroot2);
    float*          pScore2=sym_addr<float>(g_score2);

    cudaFuncSetAttribute(k_cov_wmma, cudaFuncAttributeMaxDynamicSharedMemorySize, COV_SMEM_TOTAL);

    // Stage 0: correlation adjacency (wmma bf16 HMMA)
    k_center_norm<<<BB * NNODE / 8, 256>>>(input);
    k_cov_wmma<<<dim3(8, 8, BB), 256, COV_SMEM_TOTAL>>>(pY, pA);
    k_compact<<<(BB * NNODE * 32 + 255) / 256, 256>>>(pA, pNbr, pDeg, NNODE, BB * NNODE);

    // Stage 1: SAGEConv1 + relu
    k_agg_w<7><<<BB * NNODE / 8, 256>>>(input, pNbr, pDeg, pAgg1, NNODE, FIN);
    k_sage_gemm128<<<BB * NNODE / 128, 256>>>(pAgg1, input, W1l, W1r, b1l, pH1, FIN, HH);

    // Stage 2: SAGPool1
    k_score_pre<<<(BB * NNODE * 32 + 255) / 256, 256>>>(pH1, Wp1_rel, Wp1_root, pSrel, pSroot, HH, BB * NNODE);
    k_score_agg<<<(BB * NNODE * 32 + 255) / 256, 256>>>(pSrel, pSroot, pNbr, pDeg, bp1_rel, pScore, NNODE, BB * NNODE);
    k_topk1<<<BB, NNODE>>>(pScore);
    k_nbr2<<<dim3(KK1 / 8, BB), 256>>>();

    // Stage 3: SAGEConv2 + relu
    k_agg_w<4><<<BB * KK1 / 8, 256>>>(pX1, pNbr2, pDeg2, pAgg2, KK1, HH);
    k_sage_gemm<<<dim3(BB * KK1 / 64, OO / 64), 256>>>(pAgg2, pX1, W2l, W2r, b2l, pH2, HH, OO);

    // Stage 4: SAGPool2 + global mean pool
    k_score_pre<<<(BB * KK1 * 32 + 255) / 256, 256>>>(pH2, Wp2_rel, Wp2_root, pSrel2, pSroot2, OO, BB * KK1);
    k_score_agg<<<(BB * KK1 * 32 + 255) / 256, 256>>>(pSrel2, pSroot2, pNbr2, pDeg2, bp2_rel, pScore2, KK1, BB * KK1);
    k_topk2<<<BB, KK1>>>(pScore2);
    k_pool_mean<<<BB, OO>>>();

    // Stage 5: MLP head + softmax
    k_mlp<<<BB, 512>>>(fc1_w, fc1_b, bn1_g, bn1_b, bn1_m, bn1_v,
                       fc2_w, fc2_b, bn2_g, bn2_b, bn2_m, bn2_v,
                       fc3_w, fc3_b, out);
}

// round 7
// speedup vs baseline: 1.8127x; 1.6495x over previous
#include <cuda_runtime.h>
#include <math.h>

#define BB    64
#define NNODE 1024
#define FIN   195
#define HH    128
#define OO    64
#define KK1   512
#define KK2   256
#define QW    64      // 256 int8 (padded from 195) = 64 words per row

// ---------------- scratch (device globals; no allocation allowed) ----------------
__device__ unsigned       g_q8[(size_t)BB*NNODE*QW];     // per-row-scaled int8, padded
__device__ float          g_s[BB*NNODE];                 // per-row quant scale
__device__ unsigned char  g_A[(size_t)BB*NNODE*NNODE];
__device__ unsigned short g_nbr[(size_t)BB*NNODE*NNODE];
__device__ int            g_deg[BB*NNODE];
__device__ float          g_U[(size_t)BB*NNODE*HH];
__device__ float          g_V[(size_t)BB*NNODE*HH];
__device__ float          g_h1[(size_t)BB*NNODE*HH];
__device__ float          g_srel[BB*NNODE];
__device__ float          g_sroot[BB*NNODE];
__device__ float          g_score[BB*NNODE];
__device__ int            g_idx1[BB*KK1];
__device__ float          g_x1[(size_t)BB*KK1*HH];
__device__ unsigned short g_nbr2[(size_t)BB*KK1*KK1];
__device__ int            g_deg2[BB*KK1];
__device__ float          g_U2[(size_t)BB*KK1*OO];
__device__ float          g_V2[(size_t)BB*KK1*OO];
__device__ float          g_h2[(size_t)BB*KK1*OO];
__device__ float          g_srel2[BB*KK1];
__device__ float          g_sroot2[BB*KK1];
__device__ float          g_score2[BB*KK1];
__device__ int            g_idx2[BB*KK2];
__device__ float          g_tanh2[BB*KK2];
__device__ float          g_pool[BB*OO];

// ---------------- 1) center + normalize + int8 quantize (warp per row) ----------------
__global__ void k_center_q8(const float* __restrict__ x) {
    int row = blockIdx.x * 8 + (threadIdx.x >> 5);
    int lane = threadIdx.x & 31;
    const float* xr = x + (size_t)row * FIN;
    float v[8];
    float sum = 0.f;
#pragma unroll
    for (int j = 0; j < 8; j++) {
        int f = lane * 8 + j;
        v[j] = (f < FIN) ? xr[f] : 0.f;
        sum += v[j];
    }
#pragma unroll
    for (int o = 16; o; o >>= 1) sum += __shfl_xor_sync(0xffffffffu, sum, o);
    float mean = sum * (1.0f / FIN);
    float ssq = 0.f;
#pragma unroll
    for (int j = 0; j < 8; j++) {
        int f = lane * 8 + j;
        float c = (f < FIN) ? (v[j] - mean) : 0.f;
        v[j] = c;
        ssq += c * c;
    }
#pragma unroll
    for (int o = 16; o; o >>= 1) ssq += __shfl_xor_sync(0xffffffffu, ssq, o);
    float rinv = rsqrtf(fmaxf(ssq, 1e-12f));
    float mx = 0.f;
#pragma unroll
    for (int j = 0; j < 8; j++) {
        v[j] *= rinv;
        mx = fmaxf(mx, fabsf(v[j]));
    }
#pragma unroll
    for (int o = 16; o; o >>= 1) mx = fmaxf(mx, __shfl_xor_sync(0xffffffffu, mx, o));
    float s = (mx > 0.f) ? 127.f / mx : 0.f;
    int q[8];
#pragma unroll
    for (int j = 0; j < 8; j++) {
        int t = __float2int_rn(v[j] * s);
        q[j] = max(-127, min(127, t));
    }
    unsigned w0 = (q[0] & 0xff) | ((q[1] & 0xff) << 8) | ((q[2] & 0xff) << 16) | ((q[3] & 0xff) << 24);
    unsigned w1 = (q[4] & 0xff) | ((q[5] & 0xff) << 8) | ((q[6] & 0xff) << 16) | ((q[7] & 0xff) << 24);
    unsigned long long pw = (unsigned long long)w0 | ((unsigned long long)w1 << 32);
    *(unsigned long long*)(g_q8 + (size_t)row * QW + lane * 2) = pw;
    if (lane == 0) g_s[row] = s;
}

// ---------------- 2) cov via DP4A int8: A = (dot > 0.5*s_i*s_j) ----------------
// CTA: 128x128 tile, 256 threads, 8x8 int microtile. smem As/Bs [64][132] words.
#define COV_LDW 132
#define COV_SMEM (2 * QW * COV_LDW * 4)   // 67584 B

__global__ void __launch_bounds__(256) k_cov_dp4a(unsigned char* __restrict__ Aout) {
    extern __shared__ unsigned covsm[];
    unsigned* As = covsm;
    unsigned* Bs = covsm + QW * COV_LDW;
    int b = blockIdx.z, bi = blockIdx.x, bj = blockIdx.y;
    if (bj < bi) return;
    int tid = threadIdx.x, tx = tid & 15, ty = tid >> 4;

    const unsigned* qb = g_q8 + (size_t)b * NNODE * QW;
#pragma unroll
    for (int half = 0; half < 2; half++) {
        int rowoff = (half ? bj : bi) * 128;
        unsigned* dst = half ? Bs : As;
        const unsigned* src = qb + (size_t)rowoff * QW;
#pragma unroll
        for (int p = 0; p < 32; p++) {
            int e = tid + p * 256;
            int i = e >> 6, k = e & 63;
            dst[k * COV_LDW + i] = src[i * QW + k];
        }
    }
    __syncthreads();

    int acc[8][8];
#pragma unroll
    for (int r = 0; r < 8; r++)
#pragma unroll
        for (int c = 0; c < 8; c++) acc[r][c] = 0;

    for (int kw = 0; kw < QW; kw++) {
        int a[8], bv[8];
        const unsigned* ap = As + kw * COV_LDW + ty * 8;
        const unsigned* bp = Bs + kw * COV_LDW + tx * 8;
#pragma unroll
        for (int r = 0; r < 8; r++) a[r] = (int)ap[r];
#pragma unroll
        for (int c = 0; c < 8; c++) bv[c] = (int)bp[c];
#pragma unroll
        for (int r = 0; r < 8; r++)
#pragma unroll
            for (int c = 0; c < 8; c++)
                acc[r][c] = __dp4a(a[r], bv[c], acc[r][c]);
    }

    // threshold into a bool tile (reuse As smem region)
    __syncthreads();
    unsigned char* Bt = (unsigned char*)covsm;       // [128][132] bytes
    const float* sb = g_s + b * NNODE;
    float si[8], sj[8];
#pragma unroll
    for (int r = 0; r < 8; r++) si[r] = sb[bi * 128 + ty * 8 + r];
#pragma unroll
    for (int c = 0; c < 8; c++) sj[c] = sb[bj * 128 + tx * 8 + c];
#pragma unroll
    for (int r = 0; r < 8; r++) {
        float hs = 0.5f * si[r];
#pragma unroll
        for (int c = 0; c < 8; c++)
            Bt[(ty * 8 + r) * COV_LDW + tx * 8 + c] =
                ((float)acc[r][c] > hs * sj[c]) ? 1 : 0;
    }
    __syncthreads();

    // write direct block
    {
        int r = tid >> 1, half = (tid & 1) * 64;
        unsigned char* arow = Aout + ((size_t)b * NNODE + bi * 128 + r) * NNODE + bj * 128 + half;
        const unsigned char* srow = Bt + r * COV_LDW + half;
#pragma unroll
        for (int g = 0; g < 4; g++) {
            uint4 vv;
            vv.x = *(const unsigned*)(srow + g * 16 + 0);
            vv.y = *(const unsigned*)(srow + g * 16 + 4);
            vv.z = *(const unsigned*)(srow + g * 16 + 8);
            vv.w = *(const unsigned*)(srow + g * 16 + 12);
            *(uint4*)(arow + g * 16) = vv;
        }
    }
    // write transposed block
    if (bi != bj) {
        int r = tid >> 1, half = (tid & 1) * 64;   // r = row of transposed block (= col of Bt)
        unsigned char* arow = Aout + ((size_t)b * NNODE + bj * 128 + r) * NNODE + bi * 128 + half;
#pragma unroll
        for (int g = 0; g < 16; g++) {
            unsigned wv = 0;
#pragma unroll
            for (int k2 = 0; k2 < 4; k2++)
                wv |= (unsigned)Bt[(half + g * 4 + k2) * COV_LDW + r] << (8 * k2);
            *(unsigned*)(arow + g * 4) = wv;
        }
    }
}

// ---------------- 3) compact adjacency rows (u32 loads + warp scan) ----------------
__global__ void k_compact(const unsigned char* __restrict__ A, unsigned short* __restrict__ nbr,
                          int* __restrict__ deg, int Nn, int rows) {
    int warp = (blockIdx.x * blockDim.x + threadIdx.x) >> 5;
    int lane = threadIdx.x & 31;
    if (warp >= rows) return;
    const unsigned* ar = (const unsigned*)(A + (size_t)warp * Nn);
    unsigned short* nr = nbr + (size_t)warp * Nn;
    int base = 0;
    for (int it = 0; it < Nn / 128; it++) {
        int w = it * 32 + lane;
        unsigned u = ar[w];
        int c0 = (u & 0xffu) != 0, c1 = (u & 0xff00u) != 0,
            c2 = (u & 0xff0000u) != 0, c3 = (u & 0xff000000u) != 0;
        int cnt = c0 + c1 + c2 + c3;
        int incl = cnt;
#pragma unroll
        for (int o = 1; o < 32; o <<= 1) {
            int t = __shfl_up_sync(0xffffffffu, incl, o);
            if (lane >= o) incl += t;
        }
        int pos = base + incl - cnt;
        int col = w * 4;
        if (c0) nr[pos++] = (unsigned short)(col + 0);
        if (c1) nr[pos++] = (unsigned short)(col + 1);
        if (c2) nr[pos++] = (unsigned short)(col + 2);
        if (c3) nr[pos++] = (unsigned short)(col + 3);
        base += __shfl_sync(0xffffffffu, incl, 31);
    }
    if (lane == 0) deg[warp] = base;
}

// ---------------- 4a) GEMM: out[M x 128] = X[M x K] * W^T, 128x128 tile ----------------
__global__ void __launch_bounds__(256) k_gemmNT128(
        const float* __restrict__ X, const float* __restrict__ W,
        float* __restrict__ Out, int K) {
    __shared__ float As[8][136];
    __shared__ float Bs[8][136];
    int bx = blockIdx.x;
    int tid = threadIdx.x, tx = tid & 15, ty = tid >> 4;
    float acc[8][8];
#pragma unroll
    for (int r = 0; r < 8; r++)
#pragma unroll
        for (int c = 0; c < 8; c++) acc[r][c] = 0.f;

    for (int kk = 0; kk < K; kk += 8) {
#pragma unroll
        for (int r = 0; r < 4; r++) {
            int e = tid + r * 256;
            int i = e >> 3, k = e & 7;
            float va = 0.f, vb = 0.f;
            if (kk + k < K) {
                va = X[(size_t)(bx * 128 + i) * K + kk + k];
                vb = W[(size_t)i * K + kk + k];
            }
            As[k][i] = va; Bs[k][i] = vb;
        }
        __syncthreads();
#pragma unroll
        for (int k = 0; k < 8; k++) {
            float a[8], bv[8];
#pragma unroll
            for (int r = 0; r < 8; r++) a[r] = As[k][ty * 8 + r];
#pragma unroll
            for (int c = 0; c < 8; c++) bv[c] = Bs[k][tx * 8 + c];
#pragma unroll
            for (int r = 0; r < 8; r++)
#pragma unroll
                for (int c = 0; c < 8; c++) acc[r][c] = fmaf(a[r], bv[c], acc[r][c]);
        }
        __syncthreads();
    }
#pragma unroll
    for (int r = 0; r < 8; r++) {
        int gi = bx * 128 + ty * 8 + r;
#pragma unroll
        for (int c = 0; c < 8; c++)
            Out[(size_t)gi * 128 + tx * 8 + c] = acc[r][c];
    }
}

// ---------------- 4b) GEMM: out[M x 64] = X[M x 128] * W^T, 64x64 tile ----------------
__global__ void k_gemmNT64(const float* __restrict__ X, const float* __restrict__ W,
                           float* __restrict__ Out) {
    __shared__ float As[16][68];
    __shared__ float Bs[16][68];
    int bx = blockIdx.x;
    int tid = threadIdx.x, tx = tid & 15, ty = tid >> 4;
    float acc[4][4];
#pragma unroll
    for (int r = 0; r < 4; r++)
#pragma unroll
        for (int c = 0; c < 4; c++) acc[r][c] = 0.f;

    for (int kk = 0; kk < HH; kk += 16) {
#pragma unroll
        for (int r = 0; r < 4; r++) {
            int e = tid + r * 256;
            int i = e >> 4, k = e & 15;
            As[k][i] = X[(size_t)(bx * 64 + i) * HH + kk + k];
            Bs[k][i] = (i < OO) ? W[(size_t)i * HH + kk + k] : 0.f;
        }
        __syncthreads();
#pragma unroll
        for (int k = 0; k < 16; k++) {
            float a[4], bv[4];
#pragma unroll
            for (int r = 0; r < 4; r++) a[r] = As[k][ty * 4 + r];
#pragma unroll
            for (int c = 0; c < 4; c++) bv[c] = Bs[k][tx * 4 + c];
#pragma unroll
            for (int r = 0; r < 4; r++)
#pragma unroll
                for (int c = 0; c < 4; c++) acc[r][c] = fmaf(a[r], bv[c], acc[r][c]);
        }
        __syncthreads();
    }
#pragma unroll
    for (int r = 0; r < 4; r++) {
        int gi = bx * 64 + ty * 4 + r;
#pragma unroll
        for (int c = 0; c < 4; c++) {
            int gj = tx * 4 + c;
            if (gj < OO) Out[(size_t)gi * OO + gj] = acc[r][c];
        }
    }
}

// ---------------- 5) post-aggregate stage1: h1 = relu(meanN(U) + b + V); + score pre ----------------
__global__ void k_postagg1(const float* __restrict__ bias,
                           const float* __restrict__ Wrel, const float* __restrict__ Wroot) {
    int row = blockIdx.x * 8 + (threadIdx.x >> 5);
    int lane = threadIdx.x & 31;
    int b = row >> 10;
    int dg = g_deg[row];
    const unsigned short* nr = g_nbr + (size_t)row * NNODE;
    float acc[4] = {0.f, 0.f, 0.f, 0.f};
    for (int c = 0; c < dg; c++) {
        const float* Ur = g_U + ((size_t)(b * NNODE + nr[c])) * HH;
#pragma unroll
        for (int k = 0; k < 4; k++) acc[k] += Ur[lane + 32 * k];
    }
    float inv = 1.f / fmaxf((float)dg, 1.f);
    const float* Vr = g_V + (size_t)row * HH;
    float* hr = g_h1 + (size_t)row * HH;
    float sa = 0.f, sr = 0.f;
#pragma unroll
    for (int k = 0; k < 4; k++) {
        int f = lane + 32 * k;
        float h = fmaxf(acc[k] * inv + bias[f] + Vr[f], 0.f);
        hr[f] = h;
        sa = fmaf(h, Wrel[f], sa);
        sr = fmaf(h, Wroot[f], sr);
    }
#pragma unroll
    for (int o = 16; o; o >>= 1) {
        sa += __shfl_down_sync(0xffffffffu, sa, o);
        sr += __shfl_down_sync(0xffffffffu, sr, o);
    }
    if (lane == 0) { g_srel[row] = sa; g_sroot[row] = sr; }
}

// ---------------- 5b) post-aggregate stage2 (F=64) ----------------
__global__ void k_postagg2(const float* __restrict__ bias,
                           const float* __restrict__ Wrel, const float* __restrict__ Wroot) {
    int row = blockIdx.x * 8 + (threadIdx.x >> 5);
    int lane = threadIdx.x & 31;
    int b = row / KK1;
    int dg = g_deg2[row];
    const unsigned short* nr = g_nbr2 + (size_t)row * KK1;
    float acc[2] = {0.f, 0.f};
    for (int c = 0; c < dg; c++) {
        const float* Ur = g_U2 + ((size_t)(b * KK1 + nr[c])) * OO;
#pragma unroll
        for (int k = 0; k < 2; k++) acc[k] += Ur[lane + 32 * k];
    }
    float inv = 1.f / fmaxf((float)dg, 1.f);
    const float* Vr = g_V2 + (size_t)row * OO;
    float* hr = g_h2 + (size_t)row * OO;
    float sa = 0.f, sr = 0.f;
#pragma unroll
    for (int k = 0; k < 2; k++) {
        int f = lane + 32 * k;
        float h = fmaxf(acc[k] * inv + bias[f] + Vr[f], 0.f);
        hr[f] = h;
        sa = fmaf(h, Wrel[f], sa);
        sr = fmaf(h, Wroot[f], sr);
    }
#pragma unroll
    for (int o = 16; o; o >>= 1) {
        sa += __shfl_down_sync(0xffffffffu, sa, o);
        sr += __shfl_down_sync(0xffffffffu, sr, o);
    }
    if (lane == 0) { g_srel2[row] = sa; g_sroot2[row] = sr; }
}

// ---------------- 6) score = sum_{m in N(n)} srel[m] + brel + sroot[n] ----------------
__global__ void k_score_agg(const float* __restrict__ srel, const float* __restrict__ sroot,
                            const unsigned short* __restrict__ nbr, const int* __restrict__ deg,
                            const float* __restrict__ brel, float* __restrict__ score,
                            int Nn, int rows) {
    int warp = (blockIdx.x * blockDim.x + threadIdx.x) >> 5;
    int lane = threadIdx.x & 31;
    if (warp >= rows) return;
    int b = warp / Nn;
    int dg = deg[warp];
    const unsigned short* nr = nbr + (size_t)warp * Nn;
    float a = 0.f;
    for (int c = lane; c < dg; c += 32) a += srel[b * Nn + nr[c]];
    for (int o = 16; o; o >>= 1) a += __shfl_down_sync(0xffffffffu, a, o);
    if (lane == 0) score[warp] = a + brel[0] + sroot[warp];
}

// ---------------- bitonic sort (descending, tie -> smaller idx) ----------------
__device__ __forceinline__ bool prec_cmp(float sa, int ia, float sb, int ib) {
    return (sa > sb) || (sa == sb && ia < ib);
}

template <int NSORT>
__device__ void bitonic_sort(float* s, int* id, int t) {
    for (int k = 2; k <= NSORT; k <<= 1) {
        for (int j = k >> 1; j > 0; j >>= 1) {
            int ixj = t ^ j;
            if (ixj > t) {
                float s1 = s[t], s2 = s[ixj];
                int   i1 = id[t], i2 = id[ixj];
                bool sw;
                if ((t & k) == 0) sw = prec_cmp(s2, i2, s1, i1);
                else              sw = prec_cmp(s1, i1, s2, i2);
                if (sw) { s[t] = s2; s[ixj] = s1; id[t] = i2; id[ixj] = i1; }
            }
            __syncthreads();
        }
    }
}

// ---------------- 7) top-k pool1 + gather x1 ----------------
__global__ void k_topk1(const float* __restrict__ score) {
    __shared__ float s[NNODE];
    __shared__ int   id[NNODE];
    int b = blockIdx.x, t = threadIdx.x;
    s[t] = score[b * NNODE + t];
    id[t] = t;
    __syncthreads();
    bitonic_sort<NNODE>(s, id, t);
    if (t < KK1) {
        g_idx1[b * KK1 + t] = id[t];
        s[t] = tanhf(s[t]);
    }
    __syncthreads();
    const float* h1b = g_h1 + (size_t)b * NNODE * HH;
    float* x1b = g_x1 + (size_t)b * KK1 * HH;
    for (int e = t; e < KK1 * HH; e += NNODE) {
        int k = e >> 7;
        int f = e & 127;
        x1b[e] = h1b[(size_t)id[k] * HH + f] * s[k];
    }
}

// ---------------- 8) fused: nbr2/deg2 directly from A + idx1 ----------------
__global__ void k_nbr2() {
    int b = blockIdx.y;
    int wid = threadIdx.x >> 5, lane = threadIdx.x & 31;
    int i = blockIdx.x * 8 + wid;
    __shared__ int sidx[KK1];
    for (int e = threadIdx.x; e < KK1; e += 256) sidx[e] = g_idx1[b * KK1 + e];
    __syncthreads();
    const unsigned char* ar = g_A + ((size_t)b * NNODE + sidx[i]) * NNODE;
    unsigned short* nr = g_nbr2 + ((size_t)b * KK1 + i) * KK1;
    int cnt = 0;
    for (int base = 0; base < KK1; base += 32) {
        int jj = base + lane;
        unsigned char a = ar[sidx[jj]];
        unsigned mask = __ballot_sync(0xffffffffu, a != 0);
        if (a) nr[cnt + __popc(mask & ((1u << lane) - 1u))] = (unsigned short)jj;
        cnt += __popc(mask);
    }
    if (lane == 0) g_deg2[b * KK1 + i] = cnt;
}

// ---------------- 9) top-k pool2 ----------------
__global__ void k_topk2(const float* __restrict__ score) {
    __shared__ float s[KK1];
    __shared__ int   id[KK1];
    int b = blockIdx.x, t = threadIdx.x;
    s[t] = score[b * KK1 + t];
    id[t] = t;
    __syncthreads();
    bitonic_sort<KK1>(s, id, t);
    if (t < KK2) {
        g_idx2[b * KK2 + t] = id[t];
        g_tanh2[b * KK2 + t] = tanhf(s[t]);
    }
}

// ---------------- 10) gather + scale + global mean pool ----------------
__global__ void k_pool_mean() {
    int b = blockIdx.x, f = threadIdx.x;   // 64 threads
    const float* h2b = g_h2 + (size_t)b * KK1 * OO;
    float acc = 0.f;
    for (int k = 0; k < KK2; k++)
        acc += h2b[(size_t)g_idx2[b * KK2 + k] * OO + f] * g_tanh2[b * KK2 + k];
    g_pool[b * OO + f] = acc * (1.f / KK2);
}

// ---------------- 11) MLP head ----------------
__global__ void k_mlp(const float* __restrict__ fc1_w, const float* __restrict__ fc1_b,
                      const float* __restrict__ g1, const float* __restrict__ b1,
                      const float* __restrict__ m1, const float* __restrict__ v1,
                      const float* __restrict__ fc2_w, const float* __restrict__ fc2_b,
                      const float* __restrict__ g2, const float* __restrict__ b2,
                      const float* __restrict__ m2, const float* __restrict__ v2,
                      const float* __restrict__ fc3_w, const float* __restrict__ fc3_b,
                      float* __restrict__ out) {
    int b = blockIdx.x, t = threadIdx.x;   // 512 threads
    __shared__ float sin[OO];
    __shared__ float a1[512];
    __shared__ float a2[256];
    __shared__ float lg[2];
    if (t < OO) sin[t] = g_pool[b * OO + t];
    __syncthreads();
    {
        float acc = fc1_b[t];
        const float* w = fc1_w + (size_t)t * OO;
        for (int k = 0; k < OO; k++) acc = fmaf(sin[k], w[k], acc);
        acc = fmaxf(acc, 0.f);
        a1[t] = g1[t] * (acc - m1[t]) * rsqrtf(v1[t] + 1e-5f) + b1[t];
    }
    __syncthreads();
    if (t < 256) {
        float acc = fc2_b[t];
        const float* w = fc2_w + (size_t)t * 512;
        for (int k = 0; k < 512; k++) acc = fmaf(a1[k], w[k], acc);
        acc = fmaxf(acc, 0.f);
        a2[t] = g2[t] * (acc - m2[t]) * rsqrtf(v2[t] + 1e-5f) + b2[t];
    }
    __syncthreads();
    if (t < 2) {
        float acc = fc3_b[t];
        const float* w = fc3_w + (size_t)t * 256;
        for (int k = 0; k < 256; k++) acc = fmaf(a2[k], w[k], acc);
        lg[t] = acc;
    }
    __syncthreads();
    if (t == 0) {
        float m = fmaxf(lg[0], lg[1]);
        float e0 = expf(lg[0] - m), e1 = expf(lg[1] - m);
        float inv = 1.f / (e0 + e1);
        out[b * 2 + 0] = e0 * inv;
        out[b * 2 + 1] = e1 * inv;
    }
}

// ---------------- launch ----------------
template <typename T>
static T* sym_addr(const void* symbol) {
    void* p = nullptr;
    cudaGetSymbolAddress(&p, symbol);
    return (T*)p;
}

extern "C" void kernel_launch(void* const* d_in, const int* in_sizes, int n_in,
                              void* d_out, int out_size) {
    const float* input   = (const float*)d_in[0];
    const float* W1l     = (const float*)d_in[1];
    const float* b1l     = (const float*)d_in[2];
    const float* W1r     = (const float*)d_in[3];
    const float* Wp1_rel = (const float*)d_in[4];
    const float* bp1_rel = (const float*)d_in[5];
    const float* Wp1_root= (const float*)d_in[6];
    const float* W2l     = (const float*)d_in[7];
    const float* b2l     = (const float*)d_in[8];
    const float* W2r     = (const float*)d_in[9];
    const float* Wp2_rel = (const float*)d_in[10];
    const float* bp2_rel = (const float*)d_in[11];
    const float* Wp2_root= (const float*)d_in[12];
    const float* fc1_w   = (const float*)d_in[13];
    const float* fc1_b   = (const float*)d_in[14];
    const float* bn1_g   = (const float*)d_in[15];
    const float* bn1_b   = (const float*)d_in[16];
    const float* bn1_m   = (const float*)d_in[17];
    const float* bn1_v   = (const float*)d_in[18];
    const float* fc2_w   = (const float*)d_in[19];
    const float* fc2_b   = (const float*)d_in[20];
    const float* bn2_g   = (const float*)d_in[21];
    const float* bn2_b   = (const float*)d_in[22];
    const float* bn2_m   = (const float*)d_in[23];
    const float* bn2_v   = (const float*)d_in[24];
    const float* fc3_w   = (const float*)d_in[25];
    const float* fc3_b   = (const float*)d_in[26];
    float* out = (float*)d_out;

    unsigned char*  pA    = sym_addr<unsigned char>(g_A);
    unsigned short* pNbr  = sym_addr<unsigned short>(g_nbr);
    int*            pDeg  = sym_addr<int>(g_deg);
    float*          pU    = sym_addr<float>(g_U);
    float*          pV    = sym_addr<float>(g_V);
    float*          pSrel = sym_addr<float>(g_srel);
    float*          pSroot= sym_addr<float>(g_sroot);
    float*          pScore= sym_addr<float>(g_score);
    float*          pX1   = sym_addr<float>(g_x1);
    unsigned short* pNbr2 = sym_addr<unsigned short>(g_nbr2);
    int*            pDeg2 = sym_addr<int>(g_deg2);
    float*          pU2   = sym_addr<float>(g_U2);
    float*          pV2   = sym_addr<float>(g_V2);
    float*          pSrel2= sym_addr<float>(g_srel2);
    float*          pSroot2=sym_addr<float>(g_sroot2);
    float*          pScore2=sym_addr<float>(g_score2);

    cudaFuncSetAttribute(k_cov_dp4a, cudaFuncAttributeMaxDynamicSharedMemorySize, COV_SMEM);

    // Stage 0: correlation adjacency (int8 dp4a)
    k_center_q8<<<BB * NNODE / 8, 256>>>(input);
    k_cov_dp4a<<<dim3(8, 8, BB), 256, COV_SMEM>>>(pA);
    k_compact<<<(BB * NNODE * 32 + 255) / 256, 256>>>(pA, pNbr, pDeg, NNODE, BB * NNODE);

    // Stage 1: SAGEConv1 via U = X*Wl^T, V = X*Wr^T, then neighbor-mean in output space
    k_gemmNT128<<<BB * NNODE / 128, 256>>>(input, W1l, pU, FIN);
    k_gemmNT128<<<BB * NNODE / 128, 256>>>(input, W1r, pV, FIN);
    k_postagg1<<<BB * NNODE / 8, 256>>>(b1l, Wp1_rel, Wp1_root);

    // Stage 2: SAGPool1
    k_score_agg<<<(BB * NNODE * 32 + 255) / 256, 256>>>(pSrel, pSroot, pNbr, pDeg, bp1_rel, pScore, NNODE, BB * NNODE);
    k_topk1<<<BB, NNODE>>>(pScore);
    k_nbr2<<<dim3(KK1 / 8, BB), 256>>>();

    // Stage 3: SAGEConv2 via U2 = x1*W2l^T, V2 = x1*W2r^T
    k_gemmNT64<<<BB * KK1 / 64, 256>>>(pX1, W2l, pU2);
    k_gemmNT64<<<BB * KK1 / 64, 256>>>(pX1, W2r, pV2);
    k_postagg2<<<BB * KK1 / 8, 256>>>(b2l, Wp2_rel, Wp2_root);

    // Stage 4: SAGPool2 + global mean pool
    k_score_agg<<<(BB * KK1 * 32 + 255) / 256, 256>>>(pSrel2, pSroot2, pNbr2, pDeg2, bp2_rel, pScore2, KK1, BB * KK1);
    k_topk2<<<BB, KK1>>>(pScore2);
    k_pool_mean<<<BB, OO>>>();

    // Stage 5: MLP head + softmax
    k_mlp<<<BB, 512>>>(fc1_w, fc1_b, bn1_g, bn1_b, bn1_m, bn1_v,
                       fc2_w, fc2_b, bn2_g, bn2_b, bn2_m, bn2_v,
                       fc3_w, fc3_b, out);
}